// round 1
// baseline (speedup 1.0000x reference)
#include <cuda_runtime.h>
#include <cuda_bf16.h>

#define TRUNC 2048
#define TLEN  2048
#define CAPV  200

// 8 output channels, each [2048, 2048]:
//  ch0,1 : ipow(tanh(eta[h]), L)                         h = 0,1
//  ch2   : dilate(ipow(tanh(eta[2]), .), n=4)
//  ch3,4 : sigmoid(nu[h])^L * cos(theta[h]*L)            h = 0,1
//  ch5   : sigmoid(nu[2])^L * sin(theta[2]*L)
//  ch6   : dilate(cos(theta[3]*.), n=3) * cos(theta[3]*L)
//  ch7   : dilate(sin(theta[4]*.), n=2) * sin(theta[4]*L)
// then tril(.) - eye.
// L(i,j) = |i-j| if |i-j| <= 200 else 0  -> only 201 distinct values,
// so all transcendentals collapse into a 201-entry shared table per block.

__global__ __launch_bounds__(256)
void rem_kernel(const float* __restrict__ eta,
                const float* __restrict__ nu,
                const float* __restrict__ theta,
                float* __restrict__ out)
{
    __shared__ float tab[224];

    const int ch = blockIdx.y;   // 0..7
    const int i  = blockIdx.x;   // row 0..2047
    const int t  = threadIdx.x;

    // channel config (uniform per block)
    // mode 0: plain table[Lv]
    // mode 1: dilated only           (ch2, n=4)
    // mode 2: dilated * table[Lv]    (ch6 n=3, ch7 n=2)
    int mode = 0, n = 1;
    if      (ch == 2) { mode = 1; n = 4; }
    else if (ch == 6) { mode = 2; n = 3; }
    else if (ch == 7) { mode = 2; n = 2; }

    // Build the 201-entry table of f(L)
    if (t <= CAPV) {
        float fl = (float)t;
        float v;
        if (ch < 3) {
            // ipow(tanh(eta[ch]), L): correct sign for negative base
            float lam = tanhf(eta[ch]);
            float mag = powf(fabsf(lam), fl);
            float sgn = ((t & 1) && lam < 0.0f) ? -1.0f : 1.0f;
            v = sgn * mag;
        } else if (ch < 6) {
            int h = ch - 3;                    // 0,1,2
            float gam = 1.0f / (1.0f + expf(-nu[h]));   // in (0,1), positive
            float mag = powf(gam, fl);
            float ang = theta[h] * fl;
            v = mag * ((h == 2) ? sinf(ang) : cosf(ang));
        } else {
            int h = ch - 3;                    // 3,4
            float ang = theta[h] * fl;
            v = (h == 3) ? cosf(ang) : sinf(ang);
        }
        tab[t] = v;
    }
    __syncthreads();

    const int im  = mode ? (i % n) : 0;
    const int idn = mode ? (i / n) : 0;
    float* __restrict__ row = out + ((size_t)ch * TRUNC + (size_t)i) * TLEN;

    // 2048 cols = 512 float4 per row; 256 threads x 2 iterations
    for (int jb = t * 4; jb < TLEN; jb += 256 * 4) {
        float4 r;
        float* rv = (float*)&r;
        #pragma unroll
        for (int k = 0; k < 4; k++) {
            int j = jb + k;
            int d = abs(i - j);
            int Lv = (d > CAPV) ? 0 : d;
            float v;
            if (mode == 0) {
                v = tab[Lv];
            } else {
                int jj = j / n;
                int dd = abs(idn - jj);
                int Ld = (dd > CAPV) ? 0 : dd;
                float dil = (im == (j % n)) ? tab[Ld] : 0.0f;
                v = (mode == 1) ? dil : dil * tab[Lv];
            }
            if (j > i)       v = 0.0f;     // tril
            else if (j == i) v -= 1.0f;    // - eye
            rv[k] = v;
        }
        ((float4*)row)[jb >> 2] = r;
    }
}

extern "C" void kernel_launch(void* const* d_in, const int* in_sizes, int n_in,
                              void* d_out, int out_size)
{
    const float* eta   = (const float*)d_in[0];
    const float* nu    = (const float*)d_in[1];
    const float* theta = (const float*)d_in[2];
    float* out = (float*)d_out;

    dim3 grid(TRUNC, 8, 1);
    rem_kernel<<<grid, 256>>>(eta, nu, theta, out);
}

// round 2
// speedup vs baseline: 2.1990x; 2.1990x over previous
#include <cuda_runtime.h>
#include <cuda_bf16.h>

#define TRUNC 2048
#define TLEN  2048
#define CAPV  200

// Precomputed per-channel tables of f(L), L in [0,200].
__device__ float g_tab[8][224];

// ---------------------------------------------------------------------------
// Kernel A: build the 8 x 201 transcendental tables (tiny).
//  ch0,1,2 : ipow(tanh(eta[ch]), L)
//  ch3,4   : sigmoid(nu[h])^L * cos(theta[h]*L)   h = ch-3
//  ch5     : sigmoid(nu[2])^L * sin(theta[2]*L)
//  ch6     : cos(theta[3]*L)
//  ch7     : sin(theta[4]*L)
// ---------------------------------------------------------------------------
__global__ void build_tab_kernel(const float* __restrict__ eta,
                                 const float* __restrict__ nu,
                                 const float* __restrict__ theta)
{
    int ch = blockIdx.x;
    int t  = threadIdx.x;
    if (t >= 224) return;
    float v = 0.0f;
    if (t <= CAPV) {
        float fl = (float)t;
        if (ch < 3) {
            float lam = tanhf(eta[ch]);
            float mag = powf(fabsf(lam), fl);
            v = ((t & 1) && lam < 0.0f) ? -mag : mag;
        } else if (ch < 6) {
            int h = ch - 3;
            float gam = 1.0f / (1.0f + expf(-nu[h]));
            float ang = theta[h] * fl;
            v = powf(gam, fl) * ((h == 2) ? sinf(ang) : cosf(ang));
        } else {
            int h = ch - 3;          // 3, 4
            float ang = theta[h] * fl;
            v = (h == 3) ? cosf(ang) : sinf(ang);
        }
    }
    g_tab[ch][t] = v;
}

// ---------------------------------------------------------------------------
// Kernel B: region-structured row fill. One block = one (row, channel).
// d = i - j.  Regions per channel:
//   all channels: j > i          -> 0
//   ch0,1,3,4,5 : d > 200        -> tab[0]           (constant)
//   ch2 (n=4)   : d > ~803       -> (d%4==0)?1:0     (constant float4 pattern)
//   ch6 (n=3)   : d > ~604       -> (d%3==0)?1:0     (inline pattern)
//   ch7 (n=2)   : d > 200        -> 0                (sin(0)=0 kills it)
// Narrow bands take the general compute path (table lookups).
// Diagonal: generic v -= 1 at d == 0.
// ---------------------------------------------------------------------------
__global__ __launch_bounds__(256)
void rem_fill_kernel(float* __restrict__ out)
{
    const int i  = blockIdx.x;   // row
    const int ch = blockIdx.y;   // channel
    const int t  = threadIdx.x;
    const float* __restrict__ tab = g_tab[ch];
    float4* __restrict__ row4 =
        (float4*)(out + ((size_t)ch * TRUNC + (size_t)i) * TLEN);
    const float4 zero4 = make_float4(0.f, 0.f, 0.f, 0.f);

    if (ch == 2) {
        // dilated ipow, n = 4
        float4 pat = zero4;
        ((float*)&pat)[i & 3] = 1.0f;          // far pattern: 1 at j%4 == i%4
        #pragma unroll
        for (int it = 0; it < 2; it++) {
            int q  = t + (it << 8);
            int jb = q << 2;
            float4 r;
            if (jb > i)             r = zero4;
            else if (jb < i - 806)  r = pat;
            else {
                #pragma unroll
                for (int k = 0; k < 4; k++) {
                    int d = i - jb - k;
                    float v = 0.0f;
                    if (d >= 0 && (d & 3) == 0) {
                        int dq = d >> 2;
                        int Ld = (dq > CAPV) ? 0 : dq;
                        v = __ldg(&tab[Ld]);
                        if (d == 0) v -= 1.0f;
                    }
                    ((float*)&r)[k] = v;
                }
            }
            __stcs(&row4[q], r);
        }
    } else if (ch == 6) {
        // dilated cos * cos, n = 3
        #pragma unroll
        for (int it = 0; it < 2; it++) {
            int q  = t + (it << 8);
            int jb = q << 2;
            float4 r;
            if (jb > i) {
                r = zero4;
            } else if (jb < i - 608) {
                #pragma unroll
                for (int k = 0; k < 4; k++) {
                    unsigned d = (unsigned)(i - jb - k);
                    ((float*)&r)[k] = (d % 3u == 0u) ? 1.0f : 0.0f;
                }
            } else {
                #pragma unroll
                for (int k = 0; k < 4; k++) {
                    int d = i - jb - k;
                    float v = 0.0f;
                    if (d >= 0) {
                        unsigned ud = (unsigned)d;
                        if (ud % 3u == 0u) {
                            unsigned dq = ud / 3u;
                            int Ld = (dq > CAPV) ? 0 : (int)dq;
                            int Lv = (d > CAPV) ? 0 : d;
                            v = __ldg(&tab[Ld]) * __ldg(&tab[Lv]);
                        }
                        if (d == 0) v -= 1.0f;
                    }
                    ((float*)&r)[k] = v;
                }
            }
            __stcs(&row4[q], r);
        }
    } else if (ch == 7) {
        // dilated sin * sin, n = 2 : zero outside |d| <= 200 band
        #pragma unroll
        for (int it = 0; it < 2; it++) {
            int q  = t + (it << 8);
            int jb = q << 2;
            float4 r;
            if (jb > i || jb < i - 203) {
                r = zero4;
            } else {
                #pragma unroll
                for (int k = 0; k < 4; k++) {
                    int d = i - jb - k;
                    float v = 0.0f;
                    if (d >= 0 && d <= CAPV && (d & 1) == 0)
                        v = __ldg(&tab[d >> 1]) * __ldg(&tab[d]);
                    if (d == 0) v -= 1.0f;       // sin(0)^2 - 1 = -1
                    ((float*)&r)[k] = v;
                }
            }
            __stcs(&row4[q], r);
        }
    } else {
        // plain channels 0,1,3,4,5
        float t0 = __ldg(&tab[0]);
        float4 c4 = make_float4(t0, t0, t0, t0);
        #pragma unroll
        for (int it = 0; it < 2; it++) {
            int q  = t + (it << 8);
            int jb = q << 2;
            float4 r;
            if (jb > i)            r = zero4;
            else if (jb < i - 203) r = c4;
            else {
                #pragma unroll
                for (int k = 0; k < 4; k++) {
                    int d = i - jb - k;
                    float v = 0.0f;
                    if (d >= 0) {
                        int Lv = (d > CAPV) ? 0 : d;
                        v = __ldg(&tab[Lv]);
                        if (d == 0) v -= 1.0f;
                    }
                    ((float*)&r)[k] = v;
                }
            }
            __stcs(&row4[q], r);
        }
    }
}

extern "C" void kernel_launch(void* const* d_in, const int* in_sizes, int n_in,
                              void* d_out, int out_size)
{
    const float* eta   = (const float*)d_in[0];
    const float* nu    = (const float*)d_in[1];
    const float* theta = (const float*)d_in[2];
    float* out = (float*)d_out;

    build_tab_kernel<<<8, 256>>>(eta, nu, theta);
    rem_fill_kernel<<<dim3(TRUNC, 8), 256>>>(out);
}